// round 1
// baseline (speedup 1.0000x reference)
#include <cuda_runtime.h>
#include <math.h>

#define T_TOK 8192
#define DM    512
#define DFF   2048
#define NE    64
#define CAP   320   // ceil(8192*2/64 * 1.25)

// ---------------- scratch (device globals: no allocations allowed) ----------
__device__ int   g_flat_e[T_TOK * 2];
__device__ int   g_entry_slot[T_TOK * 2];
__device__ int   g_slot_tok[NE * CAP];
__device__ float g_H[(size_t)NE * CAP * DFF];   // 168 MB
__device__ float g_Y[(size_t)NE * CAP * DM];    // 42 MB

// ---------------- 1) routing: warp per token, hashes 0 and 1 ----------------
__global__ void route_kernel(const float* __restrict__ x,
                             const float* __restrict__ Wh) {
    int gw   = (blockIdx.x * blockDim.x + threadIdx.x) >> 5;
    int lane = threadIdx.x & 31;
    if (gw >= T_TOK) return;
    const float* xr = x + (size_t)gw * DM;
    float d0 = 0.f, d1 = 0.f;
    #pragma unroll
    for (int j = lane; j < DM; j += 32) {
        float v = xr[j];
        d0 = fmaf(v, Wh[j],      d0);
        d1 = fmaf(v, Wh[DM + j], d1);
    }
    #pragma unroll
    for (int o = 16; o > 0; o >>= 1) {
        d0 += __shfl_down_sync(0xffffffffu, d0, o);
        d1 += __shfl_down_sync(0xffffffffu, d1, o);
    }
    if (lane == 0) {
        // bucket = mod(int(floor(score*8)) + LAYER_ID(0), 64); &63 == python mod
        g_flat_e[2 * gw]     = ((int)floorf(d0 * 8.0f)) & 63;
        g_flat_e[2 * gw + 1] = ((int)floorf(d1 * 8.0f)) & 63;
    }
}

// ---------------- 2) order-preserving rank, single block ---------------------
__global__ void rank_kernel() {
    __shared__ int counts[NE];
    __shared__ int whist[32][NE];
    __shared__ int wpref[32][NE];
    __shared__ int ttot[NE];
    int tid  = threadIdx.x;
    int w    = tid >> 5;
    int lane = tid & 31;
    unsigned lmask = (1u << lane) - 1u;

    if (tid < NE) counts[tid] = 0;
    for (int j = tid; j < NE * CAP; j += 1024) g_slot_tok[j] = -1;
    __syncthreads();

    for (int tile = 0; tile < (T_TOK * 2) / 1024; tile++) {
        for (int j = tid; j < 32 * NE; j += 1024) (&whist[0][0])[j] = 0;
        __syncthreads();

        int i = tile * 1024 + tid;
        int e = g_flat_e[i];
        unsigned m  = __match_any_sync(0xffffffffu, e);
        int prior   = __popc(m & lmask);
        if ((m & lmask) == 0) whist[w][e] = __popc(m);   // group leader
        __syncthreads();

        if (tid < NE) {                                   // scan over 32 warps
            int s = 0;
            #pragma unroll
            for (int ww = 0; ww < 32; ww++) { wpref[ww][tid] = s; s += whist[ww][tid]; }
            ttot[tid] = s;
        }
        __syncthreads();

        int pos = counts[e] + wpref[w][e] + prior;
        if (pos < CAP) {
            g_entry_slot[i]            = e * CAP + pos;
            g_slot_tok[e * CAP + pos]  = i >> 1;          // token index
        } else {
            g_entry_slot[i] = -1;
        }
        __syncthreads();
        if (tid < NE) counts[tid] += ttot[tid];
        __syncthreads();
    }
}

// ---------------- 3) GEMM1: H = gelu(gather(x) @ W1 + b1) --------------------
// per expert: M=CAP(320) x K=512 x N=2048.  BM=64 BN=128 BK=16, 256 thr, 8x4.
__global__ __launch_bounds__(256) void gemm1_kernel(
        const float* __restrict__ x,
        const float* __restrict__ W1,
        const float* __restrict__ b1) {
    __shared__ float As[16][68];     // [k][m], padded stride 68 (16B aligned)
    __shared__ float Bs[16][128];    // [k][n]
    __shared__ int   stok[64];

    int e  = blockIdx.z;
    int m0 = blockIdx.y * 64;
    int n0 = blockIdx.x * 128;
    int tid = threadIdx.x;
    if (tid < 64) stok[tid] = g_slot_tok[e * CAP + m0 + tid];
    __syncthreads();

    const float* Wb = W1 + (size_t)e * DM * DFF;
    float acc[8][4];
    #pragma unroll
    for (int i = 0; i < 8; i++)
        #pragma unroll
        for (int j = 0; j < 4; j++) acc[i][j] = 0.f;

    int ty = tid >> 5;          // row group 0..7  (rows ty*8..ty*8+7)
    int tx = tid & 31;          // col group       (cols tx*4..tx*4+3)
    int lm = tid >> 2;          // A-load row 0..63
    int lk = (tid & 3) * 4;     // A-load k offset

    for (int k0 = 0; k0 < DM; k0 += 16) {
        {   // gathered A tile
            int tok = stok[lm];
            float4 v = make_float4(0.f, 0.f, 0.f, 0.f);
            if (tok >= 0)
                v = *(const float4*)(x + (size_t)tok * DM + k0 + lk);
            As[lk + 0][lm] = v.x; As[lk + 1][lm] = v.y;
            As[lk + 2][lm] = v.z; As[lk + 3][lm] = v.w;
        }
        #pragma unroll
        for (int r = 0; r < 2; r++) {       // B tile: 2 x float4 per thread
            int f4 = tid + r * 256;
            int kk = f4 >> 5;
            int nn = (f4 & 31) * 4;
            *(float4*)&Bs[kk][nn] =
                *(const float4*)(Wb + (size_t)(k0 + kk) * DFF + n0 + nn);
        }
        __syncthreads();
        #pragma unroll
        for (int k = 0; k < 16; k++) {
            float4 a0 = *(const float4*)&As[k][ty * 8];
            float4 a1 = *(const float4*)&As[k][ty * 8 + 4];
            float4 b  = *(const float4*)&Bs[k][tx * 4];
            float av[8] = {a0.x, a0.y, a0.z, a0.w, a1.x, a1.y, a1.z, a1.w};
            float bv[4] = {b.x, b.y, b.z, b.w};
            #pragma unroll
            for (int i = 0; i < 8; i++)
                #pragma unroll
                for (int j = 0; j < 4; j++)
                    acc[i][j] = fmaf(av[i], bv[j], acc[i][j]);
        }
        __syncthreads();
    }

    float* Hb = g_H + (size_t)e * CAP * DFF;
    int nb = n0 + tx * 4;
    float4 bias = *(const float4*)(b1 + (size_t)e * DFF + nb);
    #pragma unroll
    for (int i = 0; i < 8; i++) {
        int m = m0 + ty * 8 + i;
        float4 o;
        float h;
        h = acc[i][0] + bias.x; o.x = 0.5f * h * (1.0f + erff(h * 0.70710678118654752f));
        h = acc[i][1] + bias.y; o.y = 0.5f * h * (1.0f + erff(h * 0.70710678118654752f));
        h = acc[i][2] + bias.z; o.z = 0.5f * h * (1.0f + erff(h * 0.70710678118654752f));
        h = acc[i][3] + bias.w; o.w = 0.5f * h * (1.0f + erff(h * 0.70710678118654752f));
        *(float4*)(Hb + (size_t)m * DFF + nb) = o;
    }
}

// ---------------- 4) GEMM2: Y = H @ W2 + b2 ----------------------------------
// per expert: M=320 x K=2048 x N=512. Same tiling.
__global__ __launch_bounds__(256) void gemm2_kernel(
        const float* __restrict__ W2,
        const float* __restrict__ b2) {
    __shared__ float As[16][68];
    __shared__ float Bs[16][128];

    int e  = blockIdx.z;
    int m0 = blockIdx.y * 64;
    int n0 = blockIdx.x * 128;
    int tid = threadIdx.x;

    const float* Ab = g_H + (size_t)e * CAP * DFF;
    const float* Wb = W2 + (size_t)e * DFF * DM;
    float acc[8][4];
    #pragma unroll
    for (int i = 0; i < 8; i++)
        #pragma unroll
        for (int j = 0; j < 4; j++) acc[i][j] = 0.f;

    int ty = tid >> 5;
    int tx = tid & 31;
    int lm = tid >> 2;
    int lk = (tid & 3) * 4;

    for (int k0 = 0; k0 < DFF; k0 += 16) {
        {
            float4 v = *(const float4*)(Ab + (size_t)(m0 + lm) * DFF + k0 + lk);
            As[lk + 0][lm] = v.x; As[lk + 1][lm] = v.y;
            As[lk + 2][lm] = v.z; As[lk + 3][lm] = v.w;
        }
        #pragma unroll
        for (int r = 0; r < 2; r++) {
            int f4 = tid + r * 256;
            int kk = f4 >> 5;
            int nn = (f4 & 31) * 4;
            *(float4*)&Bs[kk][nn] =
                *(const float4*)(Wb + (size_t)(k0 + kk) * DM + n0 + nn);
        }
        __syncthreads();
        #pragma unroll
        for (int k = 0; k < 16; k++) {
            float4 a0 = *(const float4*)&As[k][ty * 8];
            float4 a1 = *(const float4*)&As[k][ty * 8 + 4];
            float4 b  = *(const float4*)&Bs[k][tx * 4];
            float av[8] = {a0.x, a0.y, a0.z, a0.w, a1.x, a1.y, a1.z, a1.w};
            float bv[4] = {b.x, b.y, b.z, b.w};
            #pragma unroll
            for (int i = 0; i < 8; i++)
                #pragma unroll
                for (int j = 0; j < 4; j++)
                    acc[i][j] = fmaf(av[i], bv[j], acc[i][j]);
        }
        __syncthreads();
    }

    float* Yb = g_Y + (size_t)e * CAP * DM;
    int nb = n0 + tx * 4;
    float4 bias = *(const float4*)(b2 + (size_t)e * DM + nb);
    #pragma unroll
    for (int i = 0; i < 8; i++) {
        int m = m0 + ty * 8 + i;
        float4 o;
        o.x = acc[i][0] + bias.x;
        o.y = acc[i][1] + bias.y;
        o.z = acc[i][2] + bias.z;
        o.w = acc[i][3] + bias.w;
        *(float4*)(Yb + (size_t)m * DM + nb) = o;
    }
}

// ---------------- 5) output gather + mean over the 2 routes ------------------
__global__ void out_kernel(float* __restrict__ out) {
    int idx = blockIdx.x * blockDim.x + threadIdx.x;     // over T*DM/4
    if (idx >= T_TOK * DM / 4) return;
    int t  = idx / (DM / 4);
    int d4 = (idx % (DM / 4)) * 4;
    int s0 = g_entry_slot[2 * t];
    int s1 = g_entry_slot[2 * t + 1];
    float4 r = make_float4(0.f, 0.f, 0.f, 0.f);
    if (s0 >= 0) {
        float4 v = *(const float4*)(g_Y + (size_t)s0 * DM + d4);
        r.x += v.x; r.y += v.y; r.z += v.z; r.w += v.w;
    }
    if (s1 >= 0) {
        float4 v = *(const float4*)(g_Y + (size_t)s1 * DM + d4);
        r.x += v.x; r.y += v.y; r.z += v.z; r.w += v.w;
    }
    r.x *= 0.5f; r.y *= 0.5f; r.z *= 0.5f; r.w *= 0.5f;
    *(float4*)(out + (size_t)idx * 4) = r;
}

// ---------------- launch ----------------------------------------------------
extern "C" void kernel_launch(void* const* d_in, const int* in_sizes, int n_in,
                              void* d_out, int out_size) {
    const float* x   = (const float*)d_in[0];  // [4,2048,512]
    const float* Wh  = (const float*)d_in[1];  // [4,512]
    const float* W1  = (const float*)d_in[2];  // [64,512,2048]
    const float* b1  = (const float*)d_in[3];  // [64,2048]
    const float* W2  = (const float*)d_in[4];  // [64,2048,512]
    const float* b2  = (const float*)d_in[5];  // [64,512]
    float* out = (float*)d_out;

    route_kernel<<<T_TOK / 8, 256>>>(x, Wh);
    rank_kernel<<<1, 1024>>>();
    gemm1_kernel<<<dim3(DFF / 128, CAP / 64, NE), 256>>>(x, W1, b1);
    gemm2_kernel<<<dim3(DM / 128, CAP / 64, NE), 256>>>(W2, b2);
    out_kernel<<<(T_TOK * DM / 4 + 255) / 256, 256>>>(out);
}